// round 3
// baseline (speedup 1.0000x reference)
#include <cuda_runtime.h>

// SNN forward: B=128, T=1000, F=20, H=256, O=200.
// Batch elements are independent -> 1 CTA per batch element, persistent loop over T.
// Spikes are binary -> recurrent/feedforward matvecs become sparse row gather-sums.

#define Bt 128
#define Tt 1000
#define Ft 20
#define Ht 256
#define Ot 200

// Preprocessed weights (diag-zeroed Vrec, transposed W2/Wout), L2-resident (~968KB).
__device__ float g_V1[Ht * Ht];
__device__ float g_V2[Ht * Ht];
__device__ float g_W2T[Ht * Ht];   // W2T[h][g] = W2[g][h]
__device__ float g_WoT[Ht * Ot];   // WoT[h][o] = Wout[o][h]

__global__ void snn_prep(const float* __restrict__ V1, const float* __restrict__ V2,
                         const float* __restrict__ W2, const float* __restrict__ Wout) {
    int i = blockIdx.x * blockDim.x + threadIdx.x;
    if (i < Ht * Ht) {
        int r = i >> 8, c = i & 255;
        float z = (r == c) ? 0.0f : 1.0f;
        g_V1[i] = V1[i] * z;
        g_V2[i] = V2[i] * z;
        g_W2T[i] = W2[c * Ht + r];
    }
    if (i < Ht * Ot) {
        int h = i / Ot, o = i - h * Ot;
        g_WoT[i] = Wout[o * Ht + h];
    }
}

// Dynamic SMEM layout (floats):
//   xs   [20000]  : x[b] full sequence
//   w1t  [5120]   : W1 transposed [F][H]
//   P    [1024]   : 4 partial accumulators x 256 (gather combine buffer)
//   l1   [512]    : ping-pong active lists layer1 (int)
//   l2   [512]    : ping-pong active lists layer2 (int)
//   wc   [8]      : per-warp spike counts (int)
//   ncnt [4]      : list sizes n1[2], n2[2] (int)
//   wred [8]      : softmax reduction scratch
#define SMEM_FLOATS (20000 + 5120 + 1024 + 512 + 512 + 8 + 4 + 8)
#define SMEM_BYTES  (SMEM_FLOATS * 4)

__global__ __launch_bounds__(256, 1)
void snn_main(const float* __restrict__ x, const float* __restrict__ W1,
              const float* __restrict__ b1, const float* __restrict__ beta1,
              const float* __restrict__ b2, const float* __restrict__ beta2,
              const float* __restrict__ alpha_out, const float* __restrict__ beta_out,
              float* __restrict__ out) {
    extern __shared__ float sm[];
    float* xs   = sm;                       // 20000
    float* w1t  = sm + 20000;               // 5120
    float* P    = sm + 25120;               // 1024 (16B aligned: 25120*4 % 16 == 0)
    int*   l1   = (int*)(sm + 26144);       // 512
    int*   l2   = l1 + 512;                 // 512
    int*   wc   = l2 + 512;                 // 8
    int*   ncnt = wc + 8;                   // 4
    float* wred = (float*)(ncnt + 4);       // 8

    const int tid  = threadIdx.x;
    const int b    = blockIdx.x;
    const int grp  = tid >> 6;              // gather row-group 0..3
    const int lg   = tid & 63;              // lane within group (float4 column)
    const int wid  = tid >> 5, lane = tid & 31;

    // Stage x[b] (80KB) into SMEM, coalesced float4.
    {
        const float4* xb4 = (const float4*)(x + (size_t)b * (Tt * Ft));
        float4* xs4 = (float4*)xs;
        for (int i = tid; i < (Tt * Ft) / 4; i += 256) xs4[i] = xb4[i];
    }
    // W1 transposed [F][H] for conflict-free SMEM reads.
    for (int i = tid; i < Ft * Ht; i += 256) {
        int f = i >> 8, h = i & 255;
        w1t[i] = W1[h * Ft + f];
    }
    if (tid < 4) ncnt[tid] = 0;

    float syn1 = 0.f, mem1 = 0.f, spk1 = 0.f;
    float syn2 = 0.f, mem2 = 0.f, spk2 = 0.f;
    float synO = 0.f, memO = 0.f, spkO = 0.f, accO = 0.f;
    const float b1r = b1[tid], b2r = b2[tid];
    const float be1 = beta1[tid], be2 = beta2[tid];
    float aOr = 0.f, bOr = 0.f;
    if (tid < Ot) { aOr = alpha_out[tid]; bOr = beta_out[tid]; }
    __syncthreads();

    for (int t = 0; t < Tt; t++) {
        const int p = t & 1, q = p ^ 1;
        const int n1o = ncnt[q];        // layer1 active count at t-1
        const int n2o = ncnt[2 + q];    // layer2 active count at t-1

        // ---- phase 1: layer1 recurrent gather: sum Vrec1z rows over spk1(t-1) ----
        {
            float4 a = make_float4(0.f, 0.f, 0.f, 0.f);
            const float* base = g_V1 + 4 * lg;
            const int* lst = l1 + q * 256;
            #pragma unroll 4
            for (int j = grp; j < n1o; j += 4) {
                float4 v = __ldg((const float4*)(base + (lst[j] << 8)));
                a.x += v.x; a.y += v.y; a.z += v.z; a.w += v.w;
            }
            *(float4*)(P + grp * 256 + 4 * lg) = a;
        }
        __syncthreads();

        // ---- phase 2: layer1 neuron update (thread tid = neuron h) ----
        float wx = b1r;
        {
            const float* xt = xs + t * Ft;
            #pragma unroll
            for (int f = 0; f < Ft; f++) wx = fmaf(xt[f], w1t[f * Ht + tid], wx);
        }
        float act1 = wx + ((P[tid] + P[256 + tid]) + (P[512 + tid] + P[768 + tid]));
        syn1 = 0.95f * syn1 + act1;
        mem1 = be1 * mem1 + syn1 - spk1;          // THR = 1
        spk1 = (mem1 - 1.0f) > 0.f ? 1.f : 0.f;

        unsigned bal = __ballot_sync(0xffffffffu, spk1 != 0.f);
        if (lane == 0) wc[wid] = __popc(bal);
        __syncthreads();
        int off = 0, tot = 0;
        #pragma unroll
        for (int w = 0; w < 8; w++) { int c = wc[w]; off += (w < wid) ? c : 0; tot += c; }
        if (spk1 != 0.f) l1[p * 256 + off + __popc(bal & ((1u << lane) - 1u))] = tid;
        if (tid == 0) ncnt[p] = tot;
        const int n1n = tot;
        __syncthreads();

        // ---- phase 3: layer2 drive: W2T rows over spk1(t) + Vrec2z rows over spk2(t-1) ----
        {
            float4 a = make_float4(0.f, 0.f, 0.f, 0.f);
            const float* baseA = g_W2T + 4 * lg;
            const int* lstA = l1 + p * 256;
            #pragma unroll 4
            for (int j = grp; j < n1n; j += 4) {
                float4 v = __ldg((const float4*)(baseA + (lstA[j] << 8)));
                a.x += v.x; a.y += v.y; a.z += v.z; a.w += v.w;
            }
            const float* baseB = g_V2 + 4 * lg;
            const int* lstB = l2 + q * 256;
            #pragma unroll 4
            for (int j = grp; j < n2o; j += 4) {
                float4 v = __ldg((const float4*)(baseB + (lstB[j] << 8)));
                a.x += v.x; a.y += v.y; a.z += v.z; a.w += v.w;
            }
            *(float4*)(P + grp * 256 + 4 * lg) = a;
        }
        __syncthreads();

        // ---- phase 4: layer2 neuron update ----
        float act2 = b2r + ((P[tid] + P[256 + tid]) + (P[512 + tid] + P[768 + tid]));
        syn2 = 0.95f * syn2 + act2;
        mem2 = be2 * mem2 + syn2 - spk2;
        spk2 = (mem2 - 1.0f) > 0.f ? 1.f : 0.f;

        bal = __ballot_sync(0xffffffffu, spk2 != 0.f);
        if (lane == 0) wc[wid] = __popc(bal);
        __syncthreads();
        off = 0; tot = 0;
        #pragma unroll
        for (int w = 0; w < 8; w++) { int c = wc[w]; off += (w < wid) ? c : 0; tot += c; }
        if (spk2 != 0.f) l2[p * 256 + off + __popc(bal & ((1u << lane) - 1u))] = tid;
        if (tid == 0) ncnt[2 + p] = tot;
        const int n2n = tot;
        __syncthreads();

        // ---- phase 5: readout gather: WoT rows (200 wide) over spk2(t) ----
        {
            if (lg < 50) {
                float4 a = make_float4(0.f, 0.f, 0.f, 0.f);
                const float* base = g_WoT + 4 * lg;
                const int* lst = l2 + p * 256;
                #pragma unroll 4
                for (int j = grp; j < n2n; j += 4) {
                    float4 v = __ldg((const float4*)(base + lst[j] * Ot));
                    a.x += v.x; a.y += v.y; a.z += v.z; a.w += v.w;
                }
                *(float4*)(P + grp * 256 + 4 * lg) = a;
            }
        }
        __syncthreads();

        // ---- phase 6: output neurons + softmax accumulation ----
        float mval = -3.402823e38f;
        if (tid < Ot) {
            float o_t = (P[tid] + P[256 + tid]) + (P[512 + tid] + P[768 + tid]);
            synO = aOr * synO + o_t;
            memO = bOr * memO + synO - spkO;
            spkO = (memO - 1.0f) > 0.f ? 1.f : 0.f;
            mval = memO;
        }
        #pragma unroll
        for (int s = 16; s; s >>= 1) mval = fmaxf(mval, __shfl_xor_sync(0xffffffffu, mval, s));
        if (lane == 0) wred[wid] = mval;
        __syncthreads();
        float mx = fmaxf(fmaxf(fmaxf(wred[0], wred[1]), fmaxf(wred[2], wred[3])),
                         fmaxf(fmaxf(wred[4], wred[5]), fmaxf(wred[6], wred[7])));
        float ev = (tid < Ot) ? __expf(memO - mx) : 0.f;
        float sv = ev;
        #pragma unroll
        for (int s = 16; s; s >>= 1) sv += __shfl_xor_sync(0xffffffffu, sv, s);
        __syncthreads();                 // everyone done reading wred (max) before reuse
        if (lane == 0) wred[wid] = sv;
        __syncthreads();
        float ssum = ((wred[0] + wred[1]) + (wred[2] + wred[3])) +
                     ((wred[4] + wred[5]) + (wred[6] + wred[7]));
        if (tid < Ot && t > 10) accO += ev / ssum;
        // No trailing sync needed: next write to P / wred is separated by >=2 barriers.
    }

    if (tid < Ot) out[b * Ot + tid] = accO;
}

extern "C" void kernel_launch(void* const* d_in, const int* in_sizes, int n_in,
                              void* d_out, int out_size) {
    const float* x         = (const float*)d_in[0];
    const float* W1        = (const float*)d_in[1];
    const float* b1        = (const float*)d_in[2];
    const float* Vrec1     = (const float*)d_in[3];
    const float* beta1     = (const float*)d_in[4];
    const float* W2        = (const float*)d_in[5];
    const float* b2        = (const float*)d_in[6];
    const float* Vrec2     = (const float*)d_in[7];
    const float* beta2     = (const float*)d_in[8];
    const float* Wout      = (const float*)d_in[9];
    const float* alpha_out = (const float*)d_in[10];
    const float* beta_out  = (const float*)d_in[11];
    float* out = (float*)d_out;

    cudaFuncSetAttribute((const void*)snn_main,
                         cudaFuncAttributeMaxDynamicSharedMemorySize, SMEM_BYTES);

    snn_prep<<<(Ht * Ht + 255) / 256, 256>>>(Vrec1, Vrec2, W2, Wout);
    snn_main<<<Bt, 256, SMEM_BYTES>>>(x, W1, b1, beta1, b2, beta2,
                                      alpha_out, beta_out, out);
}

// round 4
// speedup vs baseline: 1.6933x; 1.6933x over previous
#include <cuda_runtime.h>

// SNN forward: B=128, T=1000, F=20, H=256, O=200.
// 1 CTA per batch element, 1024 threads, persistent loop over T.
// Spikes are binary -> matvecs become sparse row gather-sums from L2-resident weights.

#define Bt 128
#define Tt 1000
#define Ft 20
#define Ht 256
#define Ot 200
#define NTHR 1024

// Preprocessed weights (diag-zeroed Vrec, transposed W2/Wout), L2-resident (~968KB).
__device__ __align__(16) float g_V1[Ht * Ht];
__device__ __align__(16) float g_V2[Ht * Ht];
__device__ __align__(16) float g_W2T[Ht * Ht];   // W2T[h][g] = W2[g][h]
__device__ __align__(16) float g_WoT[Ht * Ot];   // WoT[h][o] = Wout[o][h]

__global__ void snn_prep(const float* __restrict__ V1, const float* __restrict__ V2,
                         const float* __restrict__ W2, const float* __restrict__ Wout) {
    int i = blockIdx.x * blockDim.x + threadIdx.x;
    if (i < Ht * Ht) {
        int r = i >> 8, c = i & 255;
        float z = (r == c) ? 0.0f : 1.0f;
        g_V1[i] = V1[i] * z;
        g_V2[i] = V2[i] * z;
        g_W2T[i] = W2[c * Ht + r];
    }
    if (i < Ht * Ot) {
        int h = i / Ot, o = i - h * Ot;
        g_WoT[i] = Wout[o * Ht + h];
    }
}

// Dynamic SMEM layout (float index):
//   w1t  [5120]       : W1 transposed [F][H]
//   PA   [8*256]      : V1 gather partials
//   PB   [8*256]      : V2 gather partials
//   PC   [16*256]     : W2T / WoT gather partials
//   l1   [512] (int)  : ping-pong active list layer1
//   l2   [512] (int)  : ping-pong active list layer2
//   wc   [8]   (int)  : per-warp spike counts
//   ncnt [4]   (int)  : n1[2], n2[2]
//   wred [8]          : softmax reduction scratch
//   xbuf [2*20]       : x(t) double buffer
#define OFF_W1T  0
#define OFF_PA   5120
#define OFF_PB   7168
#define OFF_PC   9216
#define OFF_L1   13312
#define OFF_L2   13824
#define OFF_WC   14336
#define OFF_NCNT 14344
#define OFF_WRED 14348
#define OFF_XBUF 14356
#define SMEM_FLOATS (14356 + 40)
#define SMEM_BYTES  (SMEM_FLOATS * 4)

#define NB256() asm volatile("bar.sync 1, 256;" ::: "memory")

__global__ __launch_bounds__(NTHR, 1)
void snn_main(const float* __restrict__ x, const float* __restrict__ W1,
              const float* __restrict__ b1, const float* __restrict__ beta1,
              const float* __restrict__ b2, const float* __restrict__ beta2,
              const float* __restrict__ alpha_out, const float* __restrict__ beta_out,
              float* __restrict__ out) {
    extern __shared__ float sm[];
    float* w1t  = sm + OFF_W1T;
    float* PA   = sm + OFF_PA;
    float* PB   = sm + OFF_PB;
    float* PC   = sm + OFF_PC;
    int*   l1   = (int*)(sm + OFF_L1);
    int*   l2   = (int*)(sm + OFF_L2);
    int*   wc   = (int*)(sm + OFF_WC);
    int*   ncnt = (int*)(sm + OFF_NCNT);
    float* wred = sm + OFF_WRED;
    float* xbuf = sm + OFF_XBUF;    // [2][20]

    const int tid  = threadIdx.x;
    const int b    = blockIdx.x;
    const int grp  = tid >> 6;              // 0..15
    const int lg   = tid & 63;              // float4 column within group
    const int wid  = tid >> 5, lane = tid & 31;
    const float* xb = x + (size_t)b * (Tt * Ft);

    // W1 transposed [F][H] for conflict-free SMEM reads.
    for (int i = tid; i < Ft * Ht; i += NTHR) {
        int f = i >> 8, h = i & 255;
        w1t[i] = W1[h * Ft + f];
    }
    if (tid < 4) ncnt[tid] = 0;
    if (tid < Ft) xbuf[tid] = __ldg(xb + tid);  // x(t=0)

    float syn1 = 0.f, mem1 = 0.f, spk1 = 0.f;
    float syn2 = 0.f, mem2 = 0.f, spk2 = 0.f;
    float synO = 0.f, memO = 0.f, spkO = 0.f, accO = 0.f;
    float b1r = 0.f, b2r = 0.f, be1 = 0.f, be2 = 0.f, aOr = 0.f, bOr = 0.f;
    if (tid < Ht) { b1r = b1[tid]; b2r = b2[tid]; be1 = beta1[tid]; be2 = beta2[tid]; }
    if (tid < Ot) { aOr = alpha_out[tid]; bOr = beta_out[tid]; }
    __syncthreads();

    for (int t = 0; t < Tt; t++) {
        const int p = t & 1, q = p ^ 1;
        const int n1o = ncnt[q];        // layer1 active count at t-1
        const int n2o = ncnt[2 + q];    // layer2 active count at t-1

        // prefetch x(t+1) into registers; committed to xbuf after S1
        float xnext = 0.f;
        if (tid < Ft && t + 1 < Tt) xnext = __ldg(xb + (t + 1) * Ft + tid);

        // ---- phase 1: concurrent gathers over t-1 spikes ----
        // groups 0-7:  V1 rows over l1[q]  -> PA
        // groups 8-15: V2 rows over l2[q]  -> PB
        {
            const int  g2   = grp & 7;
            const bool low  = (grp < 8);
            const float* base = (low ? g_V1 : g_V2) + 4 * lg;
            const int*   lst  = (low ? l1 : l2) + q * 256;
            const int    n    = low ? n1o : n2o;
            float4 a = make_float4(0.f, 0.f, 0.f, 0.f);
            #pragma unroll 4
            for (int j = g2; j < n; j += 8) {
                float4 v = __ldg((const float4*)(base + (lst[j] << 8)));
                a.x += v.x; a.y += v.y; a.z += v.z; a.w += v.w;
            }
            float* dst = (low ? PA : PB) + g2 * 256 + 4 * lg;
            *(float4*)dst = a;
        }
        __syncthreads();                                        // S1
        if (tid < Ft && t + 1 < Tt) xbuf[((t + 1) & 1) * Ft + tid] = xnext;

        // ---- phase 2: layer1 neuron update + spike list (warps 0-7 only) ----
        if (tid < Ht) {
            float wx = b1r;
            const float* xt = xbuf + p * Ft;
            #pragma unroll
            for (int f = 0; f < Ft; f++) wx = fmaf(xt[f], w1t[f * Ht + tid], wx);
            float s = 0.f;
            #pragma unroll
            for (int g = 0; g < 8; g++) s += PA[g * 256 + tid];
            syn1 = 0.95f * syn1 + (wx + s);
            mem1 = be1 * mem1 + syn1 - spk1;                    // THR = 1, detached reset
            spk1 = (mem1 - 1.0f) > 0.f ? 1.f : 0.f;

            unsigned bal = __ballot_sync(0xffffffffu, spk1 != 0.f);
            if (lane == 0) wc[wid] = __popc(bal);
            NB256();
            int off = 0, tot = 0;
            #pragma unroll
            for (int w = 0; w < 8; w++) { int c = wc[w]; off += (w < wid) ? c : 0; tot += c; }
            if (spk1 != 0.f) l1[p * 256 + off + __popc(bal & ((1u << lane) - 1u))] = tid;
            if (tid == 0) ncnt[p] = tot;
        }
        __syncthreads();                                        // S3
        const int n1 = ncnt[p];

        // ---- phase 3: layer2 input drive: W2T rows over l1[p], all 16 groups -> PC ----
        {
            float4 a = make_float4(0.f, 0.f, 0.f, 0.f);
            const float* base = g_W2T + 4 * lg;
            const int*   lst  = l1 + p * 256;
            #pragma unroll 4
            for (int j = grp; j < n1; j += 16) {
                float4 v = __ldg((const float4*)(base + (lst[j] << 8)));
                a.x += v.x; a.y += v.y; a.z += v.z; a.w += v.w;
            }
            *(float4*)(PC + grp * 256 + 4 * lg) = a;
        }
        __syncthreads();                                        // S4

        // ---- phase 4: layer2 neuron update + spike list (warps 0-7) ----
        if (tid < Ht) {
            float s = 0.f;
            #pragma unroll
            for (int g = 0; g < 8; g++)  s += PB[g * 256 + tid];
            #pragma unroll
            for (int g = 0; g < 16; g++) s += PC[g * 256 + tid];
            syn2 = 0.95f * syn2 + (b2r + s);
            mem2 = be2 * mem2 + syn2 - spk2;
            spk2 = (mem2 - 1.0f) > 0.f ? 1.f : 0.f;

            unsigned bal = __ballot_sync(0xffffffffu, spk2 != 0.f);
            if (lane == 0) wc[wid] = __popc(bal);
            NB256();
            int off = 0, tot = 0;
            #pragma unroll
            for (int w = 0; w < 8; w++) { int c = wc[w]; off += (w < wid) ? c : 0; tot += c; }
            if (spk2 != 0.f) l2[p * 256 + off + __popc(bal & ((1u << lane) - 1u))] = tid;
            if (tid == 0) ncnt[2 + p] = tot;
        }
        __syncthreads();                                        // S6
        const int n2 = ncnt[2 + p];

        // ---- phase 5: readout gather: WoT rows (200 wide) over l2[p] -> PC ----
        if (lg < 50) {
            float4 a = make_float4(0.f, 0.f, 0.f, 0.f);
            const float* base = g_WoT + 4 * lg;
            const int*   lst  = l2 + p * 256;
            #pragma unroll 4
            for (int j = grp; j < n2; j += 16) {
                float4 v = __ldg((const float4*)(base + lst[j] * Ot));
                a.x += v.x; a.y += v.y; a.z += v.z; a.w += v.w;
            }
            *(float4*)(PC + grp * 256 + 4 * lg) = a;
        }
        __syncthreads();                                        // S7

        // ---- phase 6: output neurons + softmax (warps 0-7; warps 8-31 run ahead) ----
        if (tid < Ht) {
            float mval = -3.402823e38f;
            if (tid < Ot) {
                float o_t = 0.f;
                #pragma unroll
                for (int g = 0; g < 16; g++) o_t += PC[g * 256 + tid];
                synO = aOr * synO + o_t;
                memO = bOr * memO + synO - spkO;
                spkO = (memO - 1.0f) > 0.f ? 1.f : 0.f;
                mval = memO;
            }
            #pragma unroll
            for (int s = 16; s; s >>= 1) mval = fmaxf(mval, __shfl_xor_sync(0xffffffffu, mval, s));
            if (lane == 0) wred[wid] = mval;
            NB256();
            float mx = fmaxf(fmaxf(fmaxf(wred[0], wred[1]), fmaxf(wred[2], wred[3])),
                             fmaxf(fmaxf(wred[4], wred[5]), fmaxf(wred[6], wred[7])));
            float ev = (tid < Ot) ? __expf(memO - mx) : 0.f;
            float sv = ev;
            #pragma unroll
            for (int s = 16; s; s >>= 1) sv += __shfl_xor_sync(0xffffffffu, sv, s);
            NB256();                      // all warps 0-7 done reading wred (max)
            if (lane == 0) wred[wid] = sv;
            NB256();
            float ssum = ((wred[0] + wred[1]) + (wred[2] + wred[3])) +
                         ((wred[4] + wred[5]) + (wred[6] + wred[7]));
            if (tid < Ot && t > 10) accO += ev / ssum;
        }
        // No trailing full barrier: warps 8-31 start next-step gathers (PA/PB, lists
        // written before S6) while warps 0-7 finish softmax; S1 re-converges them.
    }

    if (tid < Ot) out[b * Ot + tid] = accO;
}

extern "C" void kernel_launch(void* const* d_in, const int* in_sizes, int n_in,
                              void* d_out, int out_size) {
    const float* x         = (const float*)d_in[0];
    const float* W1        = (const float*)d_in[1];
    const float* b1        = (const float*)d_in[2];
    const float* Vrec1     = (const float*)d_in[3];
    const float* beta1     = (const float*)d_in[4];
    const float* W2        = (const float*)d_in[5];
    const float* b2        = (const float*)d_in[6];
    const float* Vrec2     = (const float*)d_in[7];
    const float* beta2     = (const float*)d_in[8];
    const float* Wout      = (const float*)d_in[9];
    const float* alpha_out = (const float*)d_in[10];
    const float* beta_out  = (const float*)d_in[11];
    float* out = (float*)d_out;

    cudaFuncSetAttribute((const void*)snn_main,
                         cudaFuncAttributeMaxDynamicSharedMemorySize, SMEM_BYTES);

    snn_prep<<<(Ht * Ht + 255) / 256, 256>>>(Vrec1, Vrec2, W2, Wout);
    snn_main<<<Bt, NTHR, SMEM_BYTES>>>(x, W1, b1, beta1, b2, beta2,
                                       alpha_out, beta_out, out);
}

// round 5
// speedup vs baseline: 1.7281x; 1.0205x over previous
#include <cuda_runtime.h>

// SNN forward: B=128, T=1000, F=20, H=256, O=200.
// 1 CTA per batch element, 1024 threads, persistent loop over T.
// Spikes are binary -> matvecs become sparse row gather-sums from L2-resident weights.
// Step t: phase1 gathers V1/V2/WoT over t-1 spikes concurrently; softmax(t-1) runs
// in parallel with the layer1 update on disjoint warps; then W2T gather + update2.

#define Bt 128
#define Tt 1000
#define Ft 20
#define Ht 256
#define Ot 200
#define NTHR 1024

// Preprocessed weights (diag-zeroed Vrec, transposed W2/Wout), L2-resident (~968KB).
__device__ __align__(16) float g_V1[Ht * Ht];
__device__ __align__(16) float g_V2[Ht * Ht];
__device__ __align__(16) float g_W2T[Ht * Ht];   // W2T[h][g] = W2[g][h]
__device__ __align__(16) float g_WoT[Ht * Ot];   // WoT[h][o] = Wout[o][h]

__global__ void snn_prep(const float* __restrict__ V1, const float* __restrict__ V2,
                         const float* __restrict__ W2, const float* __restrict__ Wout) {
    int i = blockIdx.x * blockDim.x + threadIdx.x;
    if (i < Ht * Ht) {
        int r = i >> 8, c = i & 255;
        float z = (r == c) ? 0.0f : 1.0f;
        g_V1[i] = V1[i] * z;
        g_V2[i] = V2[i] * z;
        g_W2T[i] = W2[c * Ht + r];
    }
    if (i < Ht * Ot) {
        int h = i / Ot, o = i - h * Ot;
        g_WoT[i] = Wout[o * Ht + h];
    }
}

// Dynamic SMEM layout (float index):
#define OFF_W1T  0        // [5120]  W1 transposed [F][H]
#define OFF_PA   5120     // [6*256] V1 gather partials
#define OFF_PB   6656     // [6*256] V2 gather partials
#define OFF_PW   8192     // [4*256] WoT gather partials
#define OFF_PC   9216     // [16*256] W2T gather partials
#define OFF_L1   13312    // [512] int: ping-pong active list layer1
#define OFF_L2   13824    // [512] int: ping-pong active list layer2
#define OFF_WC   14336    // [8]   int: per-warp spike counts
#define OFF_NCNT 14344    // [4]   int: n1[2], n2[2]
#define OFF_WRED 14348    // [8]   softmax reduction scratch
#define OFF_XBUF 14356    // [2*20] x(t) double buffer
#define SMEM_FLOATS (14356 + 40)
#define SMEM_BYTES  (SMEM_FLOATS * 4)

#define NB_L1()  asm volatile("bar.sync 1, 256;" ::: "memory")   // warps 0-7
#define NB_SMX() asm volatile("bar.sync 2, 224;" ::: "memory")   // warps 8-14

__global__ __launch_bounds__(NTHR, 1)
void snn_main(const float* __restrict__ x, const float* __restrict__ W1,
              const float* __restrict__ b1, const float* __restrict__ beta1,
              const float* __restrict__ b2, const float* __restrict__ beta2,
              const float* __restrict__ alpha_out, const float* __restrict__ beta_out,
              float* __restrict__ out) {
    extern __shared__ float sm[];
    float* w1t  = sm + OFF_W1T;
    float* PA   = sm + OFF_PA;
    float* PB   = sm + OFF_PB;
    float* PW   = sm + OFF_PW;
    float* PC   = sm + OFF_PC;
    int*   l1   = (int*)(sm + OFF_L1);
    int*   l2   = (int*)(sm + OFF_L2);
    int*   wc   = (int*)(sm + OFF_WC);
    int*   ncnt = (int*)(sm + OFF_NCNT);
    float* wred = sm + OFF_WRED;
    float* xbuf = sm + OFF_XBUF;

    const int tid  = threadIdx.x;
    const int b    = blockIdx.x;
    const int grp  = tid >> 6;              // 0..15 (64-thread row groups)
    const int lg   = tid & 63;              // float4 column within row
    const int wid  = tid >> 5, lane = tid & 31;
    const float* xb = x + (size_t)b * (Tt * Ft);

    for (int i = tid; i < Ft * Ht; i += NTHR) {       // W1^T [F][H]
        int f = i >> 8, h = i & 255;
        w1t[i] = W1[h * Ft + f];
    }
    if (tid < 4) ncnt[tid] = 0;
    if (tid < Ft) xbuf[tid] = __ldg(xb + tid);

    // Layer-neuron state on threads 0-255; output-neuron state on threads 256-455.
    float syn1 = 0.f, mem1 = 0.f, spk1 = 0.f;
    float syn2 = 0.f, mem2 = 0.f, spk2 = 0.f;
    float synO = 0.f, memO = 0.f, spkO = 0.f, accO = 0.f;
    float b1r = 0.f, b2r = 0.f, be1 = 0.f, be2 = 0.f, aOr = 0.f, bOr = 0.f;
    if (tid < Ht) { b1r = b1[tid]; b2r = b2[tid]; be1 = beta1[tid]; be2 = beta2[tid]; }
    const int oo = tid - 256;                          // output index for warps 8-14
    if (oo >= 0 && oo < Ot) { aOr = alpha_out[oo]; bOr = beta_out[oo]; }
    __syncthreads();

    // Loop runs Tt+1 iterations: iteration t does updates for step t (t<Tt) and
    // readout/softmax for step t-1 (t>=1).
    for (int t = 0; t <= Tt; t++) {
        const int p = t & 1, q = p ^ 1;
        const int n1o = ncnt[q];
        const int n2o = ncnt[2 + q];

        float xnext = 0.f;
        if (tid < Ft && t + 1 < Tt) xnext = __ldg(xb + (t + 1) * Ft + tid);

        // ---- phase 1: concurrent gathers over (t-1) spikes ----
        // groups 0-5: V1 rows over l1[q] -> PA ; 6-11: V2 over l2[q] -> PB ;
        // groups 12-15 (lg<50): WoT (200-wide) over l2[q] -> PW.
        if (grp < 12) {
            const bool v1s = (grp < 6);
            const float* base = (v1s ? g_V1 : g_V2) + 4 * lg;
            const int*   lst  = (v1s ? l1 : l2) + q * 256;
            const int    n    = v1s ? n1o : n2o;
            const int    g    = v1s ? grp : grp - 6;
            float4 a = make_float4(0.f, 0.f, 0.f, 0.f);
            #pragma unroll 8
            for (int j = g; j < n; j += 6) {
                float4 v = __ldg((const float4*)(base + (lst[j] << 8)));
                a.x += v.x; a.y += v.y; a.z += v.z; a.w += v.w;
            }
            *(float4*)((v1s ? PA : PB) + g * 256 + 4 * lg) = a;
        } else if (lg < 50) {
            const int g = grp - 12;
            const float* base = g_WoT + 4 * lg;
            const int*   lst  = l2 + q * 256;
            float4 a = make_float4(0.f, 0.f, 0.f, 0.f);
            #pragma unroll 8
            for (int j = g; j < n2o; j += 4) {
                float4 v = __ldg((const float4*)(base + lst[j] * Ot));
                a.x += v.x; a.y += v.y; a.z += v.z; a.w += v.w;
            }
            *(float4*)(PW + g * 256 + 4 * lg) = a;
        }
        __syncthreads();                                        // S1
        if (tid < Ft && t + 1 < Tt) xbuf[((t + 1) & 1) * Ft + tid] = xnext;

        // ---- layer1 update + spike list (warps 0-7) ... concurrent with ...
        if (t < Tt && tid < Ht) {
            float wx = b1r;
            const float* xt = xbuf + p * Ft;
            #pragma unroll
            for (int f = 0; f < Ft; f++) wx = fmaf(xt[f], w1t[f * Ht + tid], wx);
            float s = 0.f;
            #pragma unroll
            for (int g = 0; g < 6; g++) s += PA[g * 256 + tid];
            syn1 = 0.95f * syn1 + (wx + s);
            mem1 = be1 * mem1 + syn1 - spk1;                    // THR=1, detached reset
            spk1 = (mem1 - 1.0f) > 0.f ? 1.f : 0.f;

            unsigned bal = __ballot_sync(0xffffffffu, spk1 != 0.f);
            if (lane == 0) wc[wid] = __popc(bal);
            NB_L1();
            int off = 0, tot = 0;
            #pragma unroll
            for (int w = 0; w < 8; w++) { int c = wc[w]; off += (w < wid) ? c : 0; tot += c; }
            if (spk1 != 0.f) l1[p * 256 + off + __popc(bal & ((1u << lane) - 1u))] = tid;
            if (tid == 0) ncnt[p] = tot;
        }
        // ---- ... readout + softmax for step t-1 (warps 8-14) ----
        if (t >= 1 && wid >= 8 && wid < 15) {
            float mval = -3.402823e38f;
            if (oo < Ot) {
                float o_t = ((PW[oo] + PW[256 + oo]) + (PW[512 + oo] + PW[768 + oo]));
                synO = aOr * synO + o_t;
                memO = bOr * memO + synO - spkO;
                spkO = (memO - 1.0f) > 0.f ? 1.f : 0.f;
                mval = memO;
            }
            #pragma unroll
            for (int s = 16; s; s >>= 1) mval = fmaxf(mval, __shfl_xor_sync(0xffffffffu, mval, s));
            if (lane == 0) wred[wid - 8] = mval;
            NB_SMX();
            float mx = fmaxf(fmaxf(fmaxf(wred[0], wred[1]), fmaxf(wred[2], wred[3])),
                             fmaxf(fmaxf(wred[4], wred[5]), wred[6]));
            float ev = (oo < Ot) ? __expf(memO - mx) : 0.f;
            float sv = ev;
            #pragma unroll
            for (int s = 16; s; s >>= 1) sv += __shfl_xor_sync(0xffffffffu, sv, s);
            NB_SMX();
            if (lane == 0) wred[wid - 8] = sv;
            NB_SMX();
            float ssum = (((wred[0] + wred[1]) + (wred[2] + wred[3])) +
                          ((wred[4] + wred[5]) + wred[6]));
            if (oo < Ot && t > 11) accO += ev / ssum;           // step (t-1) > WARMUP
        }
        __syncthreads();                                        // S3
        const int n1 = ncnt[p];

        // ---- W2T gather over spk1(t), all 16 groups -> PC ----
        if (t < Tt) {
            float4 a = make_float4(0.f, 0.f, 0.f, 0.f);
            const float* base = g_W2T + 4 * lg;
            const int*   lst  = l1 + p * 256;
            #pragma unroll 8
            for (int j = grp; j < n1; j += 16) {
                float4 v = __ldg((const float4*)(base + (lst[j] << 8)));
                a.x += v.x; a.y += v.y; a.z += v.z; a.w += v.w;
            }
            *(float4*)(PC + grp * 256 + 4 * lg) = a;
        }
        __syncthreads();                                        // S4

        // ---- layer2 update + spike list (warps 0-7) ----
        if (t < Tt && tid < Ht) {
            float s = 0.f;
            #pragma unroll
            for (int g = 0; g < 6; g++)  s += PB[g * 256 + tid];
            #pragma unroll
            for (int g = 0; g < 16; g++) s += PC[g * 256 + tid];
            syn2 = 0.95f * syn2 + (b2r + s);
            mem2 = be2 * mem2 + syn2 - spk2;
            spk2 = (mem2 - 1.0f) > 0.f ? 1.f : 0.f;

            unsigned bal = __ballot_sync(0xffffffffu, spk2 != 0.f);
            if (lane == 0) wc[wid] = __popc(bal);
            NB_L1();
            int off = 0, tot = 0;
            #pragma unroll
            for (int w = 0; w < 8; w++) { int c = wc[w]; off += (w < wid) ? c : 0; tot += c; }
            if (spk2 != 0.f) l2[p * 256 + off + __popc(bal & ((1u << lane) - 1u))] = tid;
            if (tid == 0) ncnt[2 + p] = tot;
        }
        __syncthreads();                                        // S6
    }

    if (oo >= 0 && oo < Ot) out[b * Ot + oo] = accO;
}

extern "C" void kernel_launch(void* const* d_in, const int* in_sizes, int n_in,
                              void* d_out, int out_size) {
    const float* x         = (const float*)d_in[0];
    const float* W1        = (const float*)d_in[1];
    const float* b1        = (const float*)d_in[2];
    const float* Vrec1     = (const float*)d_in[3];
    const float* beta1     = (const float*)d_in[4];
    const float* W2        = (const float*)d_in[5];
    const float* b2        = (const float*)d_in[6];
    const float* Vrec2     = (const float*)d_in[7];
    const float* beta2     = (const float*)d_in[8];
    const float* Wout      = (const float*)d_in[9];
    const float* alpha_out = (const float*)d_in[10];
    const float* beta_out  = (const float*)d_in[11];
    float* out = (float*)d_out;

    cudaFuncSetAttribute((const void*)snn_main,
                         cudaFuncAttributeMaxDynamicSharedMemorySize, SMEM_BYTES);

    snn_prep<<<(Ht * Ht + 255) / 256, 256>>>(Vrec1, Vrec2, W2, Wout);
    snn_main<<<Bt, NTHR, SMEM_BYTES>>>(x, W1, b1, beta1, b2, beta2,
                                       alpha_out, beta_out, out);
}

// round 6
// speedup vs baseline: 2.0080x; 1.1620x over previous
#include <cuda_runtime.h>

// SNN forward: B=128, T=1000, F=20, H=256, O=200.
// 1 CTA per batch element, 1024 threads, persistent loop.
// LAYER-PIPELINED: at loop iteration t -> layer1 computes step t, layer2 computes
// step t-1, readout computes step t-2. All gather inputs (spk1(t-1), spk2(t-2))
// are then available simultaneously -> single gather phase + 2 barriers per step.

#define Bt 128
#define Tt 1000
#define Ft 20
#define Ht 256
#define Ot 200
#define NTHR 1024

// Preprocessed weights (diag-zeroed Vrec, transposed W2/Wout), L2-resident (~968KB).
__device__ __align__(16) float g_V1[Ht * Ht];
__device__ __align__(16) float g_V2[Ht * Ht];
__device__ __align__(16) float g_W2T[Ht * Ht];   // W2T[h][g] = W2[g][h]
__device__ __align__(16) float g_WoT[Ht * Ot];   // WoT[h][o] = Wout[o][h]

__global__ void snn_prep(const float* __restrict__ V1, const float* __restrict__ V2,
                         const float* __restrict__ W2, const float* __restrict__ Wout) {
    int i = blockIdx.x * blockDim.x + threadIdx.x;
    if (i < Ht * Ht) {
        int r = i >> 8, c = i & 255;
        float z = (r == c) ? 0.0f : 1.0f;
        g_V1[i] = V1[i] * z;
        g_V2[i] = V2[i] * z;
        g_W2T[i] = W2[c * Ht + r];
    }
    if (i < Ht * Ot) {
        int h = i / Ot, o = i - h * Ot;
        g_WoT[i] = Wout[o * Ht + h];
    }
}

// Dynamic SMEM layout (float index):
#define OFF_W1T  0        // [5120]  W1 transposed [F][H]
#define OFF_PA   5120     // [4*256] V1  partials (layer1 feedback)
#define OFF_PC   6144     // [4*256] W2T partials (layer2 input drive)
#define OFF_PB   7168     // [4*256] V2  partials (layer2 feedback)
#define OFF_PW   8192     // [4*256] WoT partials (readout)
#define OFF_L1   9216     // [512] int: ping-pong spike list layer1
#define OFF_L2   9728     // [512] int: ping-pong spike list layer2
#define OFF_WC1  10240    // [8]   int: warp spike counts layer1
#define OFF_WC2  10248    // [8]   int: warp spike counts layer2
#define OFF_NCNT 10256    // [4]   int: n1[2], n2[2]
#define OFF_WRED 10260    // [8]   softmax scratch
#define OFF_XBUF 10268    // [2*20] x(t) double buffer
#define SMEM_FLOATS (10268 + 40)
#define SMEM_BYTES  (SMEM_FLOATS * 4)

#define NB1() asm volatile("bar.sync 1, 256;" ::: "memory")   // warps 0-7   (layer1)
#define NB2() asm volatile("bar.sync 3, 256;" ::: "memory")   // warps 8-15  (layer2)
#define NB3() asm volatile("bar.sync 2, 224;" ::: "memory")   // warps 16-22 (readout)

__global__ __launch_bounds__(NTHR, 1)
void snn_main(const float* __restrict__ x, const float* __restrict__ W1,
              const float* __restrict__ b1, const float* __restrict__ beta1,
              const float* __restrict__ b2, const float* __restrict__ beta2,
              const float* __restrict__ alpha_out, const float* __restrict__ beta_out,
              float* __restrict__ out) {
    extern __shared__ float sm[];
    float* w1t  = sm + OFF_W1T;
    float* PA   = sm + OFF_PA;
    float* PC   = sm + OFF_PC;
    float* PB   = sm + OFF_PB;
    float* PW   = sm + OFF_PW;
    int*   l1   = (int*)(sm + OFF_L1);
    int*   l2   = (int*)(sm + OFF_L2);
    int*   wc1  = (int*)(sm + OFF_WC1);
    int*   wc2  = (int*)(sm + OFF_WC2);
    int*   ncnt = (int*)(sm + OFF_NCNT);
    float* wred = sm + OFF_WRED;
    float* xbuf = sm + OFF_XBUF;

    const int tid  = threadIdx.x;
    const int b    = blockIdx.x;
    const int grp  = tid >> 6;              // 0..15 (64-thread row groups)
    const int g    = grp & 3;               // group within matrix
    const int mat  = grp >> 2;              // 0:V1 1:W2T 2:V2 3:WoT
    const int lg   = tid & 63;              // float4 column within row
    const int wid  = tid >> 5, lane = tid & 31;
    const float* xb = x + (size_t)b * (Tt * Ft);

    for (int i = tid; i < Ft * Ht; i += NTHR) {       // W1^T [F][H]
        int f = i >> 8, h = i & 255;
        w1t[i] = W1[h * Ft + f];
    }
    if (tid < 4) ncnt[tid] = 0;
    if (tid < Ft) xbuf[tid] = __ldg(xb + tid);        // x(0) -> slot 0

    // Role state: layer1 on tid 0-255, layer2 on tid 256-511, readout on tid 512-711.
    float syn1 = 0.f, mem1 = 0.f, spk1 = 0.f;
    float syn2 = 0.f, mem2 = 0.f, spk2 = 0.f;
    float synO = 0.f, memO = 0.f, spkO = 0.f, accO = 0.f;
    float b1r = 0.f, be1 = 0.f, b2r = 0.f, be2 = 0.f, aOr = 0.f, bOr = 0.f;
    const int h2 = tid - 256;                         // layer2 neuron index
    const int oo = tid - 512;                         // output neuron index
    if (tid < Ht)              { b1r = b1[tid]; be1 = beta1[tid]; }
    if (h2 >= 0 && h2 < Ht)    { b2r = b2[h2];  be2 = beta2[h2]; }
    if (oo >= 0 && oo < Ot)    { aOr = alpha_out[oo]; bOr = beta_out[oo]; }
    __syncthreads();

    // Iteration t: layer1 step t (t<Tt), layer2 step t-1 (1<=t<=Tt),
    // readout step t-2 (2<=t<=Tt+1). All gathers read parity q, updates write p.
    for (int t = 0; t <= Tt + 1; t++) {
        const int p = t & 1, q = p ^ 1;
        const int n1o = ncnt[q];        // |spk1(t-1)|
        const int n2o = ncnt[2 + q];    // |spk2(t-2)|

        float xnext = 0.f;
        if (tid < Ft && t + 1 < Tt) xnext = __ldg(xb + (t + 1) * Ft + tid);

        // ---- single gather phase: 4 matrices concurrently, 4 groups each ----
        if (mat == 0) {               // V1 rows over l1[q] -> PA
            if (t < Tt) {
                float4 a = make_float4(0.f, 0.f, 0.f, 0.f);
                const float* base = g_V1 + 4 * lg;
                const int*   lst  = l1 + q * 256;
                #pragma unroll 8
                for (int j = g; j < n1o; j += 4) {
                    float4 v = __ldg((const float4*)(base + (lst[j] << 8)));
                    a.x += v.x; a.y += v.y; a.z += v.z; a.w += v.w;
                }
                *(float4*)(PA + g * 256 + 4 * lg) = a;
            }
        } else if (mat == 1) {        // W2T rows over l1[q] -> PC
            if (t >= 1 && t <= Tt) {
                float4 a = make_float4(0.f, 0.f, 0.f, 0.f);
                const float* base = g_W2T + 4 * lg;
                const int*   lst  = l1 + q * 256;
                #pragma unroll 8
                for (int j = g; j < n1o; j += 4) {
                    float4 v = __ldg((const float4*)(base + (lst[j] << 8)));
                    a.x += v.x; a.y += v.y; a.z += v.z; a.w += v.w;
                }
                *(float4*)(PC + g * 256 + 4 * lg) = a;
            }
        } else if (mat == 2) {        // V2 rows over l2[q] -> PB
            if (t >= 1 && t <= Tt) {
                float4 a = make_float4(0.f, 0.f, 0.f, 0.f);
                const float* base = g_V2 + 4 * lg;
                const int*   lst  = l2 + q * 256;
                #pragma unroll 8
                for (int j = g; j < n2o; j += 4) {
                    float4 v = __ldg((const float4*)(base + (lst[j] << 8)));
                    a.x += v.x; a.y += v.y; a.z += v.z; a.w += v.w;
                }
                *(float4*)(PB + g * 256 + 4 * lg) = a;
            }
        } else {                      // WoT rows (200 wide) over l2[q] -> PW
            if (t >= 2 && lg < 50) {
                float4 a = make_float4(0.f, 0.f, 0.f, 0.f);
                const float* base = g_WoT + 4 * lg;
                const int*   lst  = l2 + q * 256;
                #pragma unroll 8
                for (int j = g; j < n2o; j += 4) {
                    float4 v = __ldg((const float4*)(base + lst[j] * Ot));
                    a.x += v.x; a.y += v.y; a.z += v.z; a.w += v.w;
                }
                *(float4*)(PW + g * 256 + 4 * lg) = a;
            }
        }
        __syncthreads();                                        // S1
        if (tid < Ft && t + 1 < Tt) xbuf[q * Ft + tid] = xnext; // slot (t+1)&1 == q

        // ---- layer1 step t (warps 0-7) ----
        if (t < Tt && tid < Ht) {
            float wx = b1r;
            const float* xt = xbuf + p * Ft;
            #pragma unroll
            for (int f = 0; f < Ft; f++) wx = fmaf(xt[f], w1t[f * Ht + tid], wx);
            float s = ((PA[tid] + PA[256 + tid]) + (PA[512 + tid] + PA[768 + tid]));
            syn1 = 0.95f * syn1 + (wx + s);
            mem1 = be1 * mem1 + syn1 - spk1;                    // THR=1, detached reset
            spk1 = (mem1 - 1.0f) > 0.f ? 1.f : 0.f;

            unsigned bal = __ballot_sync(0xffffffffu, spk1 != 0.f);
            if (lane == 0) wc1[wid] = __popc(bal);
            NB1();
            int off = 0, tot = 0;
            #pragma unroll
            for (int w = 0; w < 8; w++) { int c = wc1[w]; off += (w < wid) ? c : 0; tot += c; }
            if (spk1 != 0.f) l1[p * 256 + off + __popc(bal & ((1u << lane) - 1u))] = tid;
            if (tid == 0) ncnt[p] = tot;
        }

        // ---- layer2 step t-1 (warps 8-15) ----
        if (t >= 1 && t <= Tt && h2 >= 0 && h2 < Ht) {
            const int w2 = wid - 8;
            float s = ((PC[h2] + PC[256 + h2]) + (PC[512 + h2] + PC[768 + h2])) +
                      ((PB[h2] + PB[256 + h2]) + (PB[512 + h2] + PB[768 + h2]));
            syn2 = 0.95f * syn2 + (b2r + s);
            mem2 = be2 * mem2 + syn2 - spk2;
            spk2 = (mem2 - 1.0f) > 0.f ? 1.f : 0.f;

            unsigned bal = __ballot_sync(0xffffffffu, spk2 != 0.f);
            if (lane == 0) wc2[w2] = __popc(bal);
            NB2();
            int off = 0, tot = 0;
            #pragma unroll
            for (int w = 0; w < 8; w++) { int c = wc2[w]; off += (w < w2) ? c : 0; tot += c; }
            if (spk2 != 0.f) l2[p * 256 + off + __popc(bal & ((1u << lane) - 1u))] = h2;
            if (h2 == 0) ncnt[2 + p] = tot;
        }

        // ---- readout step t-2 (warps 16-22) ----
        if (t >= 2 && wid >= 16 && wid < 23) {
            float mval = -3.402823e38f;
            if (oo < Ot) {
                float o_t = ((PW[oo] + PW[256 + oo]) + (PW[512 + oo] + PW[768 + oo]));
                synO = aOr * synO + o_t;
                memO = bOr * memO + synO - spkO;
                spkO = (memO - 1.0f) > 0.f ? 1.f : 0.f;
                mval = memO;
            }
            #pragma unroll
            for (int s = 16; s; s >>= 1) mval = fmaxf(mval, __shfl_xor_sync(0xffffffffu, mval, s));
            if (lane == 0) wred[wid - 16] = mval;
            NB3();
            float mx = fmaxf(fmaxf(fmaxf(wred[0], wred[1]), fmaxf(wred[2], wred[3])),
                             fmaxf(fmaxf(wred[4], wred[5]), wred[6]));
            float ev = (oo < Ot) ? __expf(memO - mx) : 0.f;
            float sv = ev;
            #pragma unroll
            for (int s = 16; s; s >>= 1) sv += __shfl_xor_sync(0xffffffffu, sv, s);
            NB3();
            if (lane == 0) wred[wid - 16] = sv;
            NB3();
            float ssum = (((wred[0] + wred[1]) + (wred[2] + wred[3])) +
                          ((wred[4] + wred[5]) + wred[6]));
            if (oo < Ot && t > 12) accO += ev / ssum;           // step (t-2) > WARMUP
        }
        __syncthreads();                                        // S2
    }

    if (oo >= 0 && oo < Ot) out[b * Ot + oo] = accO;
}

extern "C" void kernel_launch(void* const* d_in, const int* in_sizes, int n_in,
                              void* d_out, int out_size) {
    const float* x         = (const float*)d_in[0];
    const float* W1        = (const float*)d_in[1];
    const float* b1        = (const float*)d_in[2];
    const float* Vrec1     = (const float*)d_in[3];
    const float* beta1     = (const float*)d_in[4];
    const float* W2        = (const float*)d_in[5];
    const float* b2        = (const float*)d_in[6];
    const float* Vrec2     = (const float*)d_in[7];
    const float* beta2     = (const float*)d_in[8];
    const float* Wout      = (const float*)d_in[9];
    const float* alpha_out = (const float*)d_in[10];
    const float* beta_out  = (const float*)d_in[11];
    float* out = (float*)d_out;

    cudaFuncSetAttribute((const void*)snn_main,
                         cudaFuncAttributeMaxDynamicSharedMemorySize, SMEM_BYTES);

    snn_prep<<<(Ht * Ht + 255) / 256, 256>>>(Vrec1, Vrec2, W2, Wout);
    snn_main<<<Bt, NTHR, SMEM_BYTES>>>(x, W1, b1, beta1, b2, beta2,
                                       alpha_out, beta_out, out);
}